// round 3
// baseline (speedup 1.0000x reference)
#include <cuda_runtime.h>
#include <cstdint>

#define T_DIM 2048
#define B_DIM 256
#define D_DIM 256
#define H_DIM 8
#define G_DIM 32
#define M_DIM (T_DIM * B_DIM)

// Scratch for x_gates (+ folded biases): [T, B, 32] fp32 = 64 MB
__device__ float g_xg[(size_t)M_DIM * G_DIM];

// ---------------------------------------------------------------------------
// Packed f32x2 FMA (sm_103a): d = a*b + d  (two independent fp32 FMAs)
// ---------------------------------------------------------------------------
__device__ __forceinline__ void fma2(unsigned long long& d,
                                     unsigned long long a,
                                     unsigned long long b) {
    asm("fma.rn.f32x2 %0, %1, %2, %0;" : "+l"(d) : "l"(a), "l"(b));
}

__device__ __forceinline__ float ex2a(float x) {
    float y; asm("ex2.approx.ftz.f32 %0, %1;" : "=f"(y) : "f"(x)); return y;
}
__device__ __forceinline__ float rcpa(float x) {
    float y; asm("rcp.approx.ftz.f32 %0, %1;" : "=f"(y) : "f"(x)); return y;
}

// ---------------------------------------------------------------------------
// GEMM: x_gates[m, g] = sum_k x[m,k] * W_ih[g,k]  + (b_ih[g] + b_hh[g])
// M = 524288, K = 256, N = 32.  f32x2 packs k-pairs.
// Block: 128 threads, 64-row tile, full K staged in smem.
// Thread: 4 rows x 4 gates (gates g0, g0+8, g0+16, g0+24; g0 = tid&7).
// Bank layout: x rows stride 258 floats (rows 4 apart -> banks 8 apart);
// W transposed to [kp][gate] float2, row stride 33 (gate g0 -> banks 2*g0).
// ---------------------------------------------------------------------------
#define GROWS 64
#define SX 258
#define SW 33
#define GEMM_SMEM (GROWS * SX * 4 + 128 * SW * 8)

__global__ void __launch_bounds__(128, 2) gemm_k(
    const float* __restrict__ x, const float* __restrict__ W_ih,
    const float* __restrict__ b_ih, const float* __restrict__ b_hh)
{
    extern __shared__ float sm[];
    float* xs = sm;                                                  // [64][SX]
    unsigned long long* ws = (unsigned long long*)(sm + GROWS * SX); // [128][SW]
    const int tid = threadIdx.x;
    const size_t row0 = (size_t)blockIdx.x * GROWS;

    // Stage W: W_ih[g][2kp..2kp+1] -> ws[kp*SW + g] (k-pair packed)
    const float2* W2 = (const float2*)W_ih;
    for (int u = tid; u < 32 * 128; u += 128) {
        int g = u >> 7, kp = u & 127;
        float2 v = W2[(size_t)g * 128 + kp];
        ((float2*)ws)[kp * SW + g] = v;
    }
    // Stage x tile (coalesced float4 loads, float2 smem stores)
    const float4* X4 = (const float4*)(x + row0 * D_DIM);
    for (int u = tid; u < GROWS * 64; u += 128) {
        int r = u >> 6, k4 = u & 63;
        float4 v = X4[(size_t)r * 64 + k4];
        float2* dst = (float2*)&xs[r * SX + k4 * 4];
        dst[0] = make_float2(v.x, v.y);
        dst[1] = make_float2(v.z, v.w);
    }
    __syncthreads();

    const int g0 = tid & 7;
    const int rb = (tid >> 3) * 4;

    unsigned long long acc[4][4];
#pragma unroll
    for (int i = 0; i < 4; i++)
#pragma unroll
        for (int j = 0; j < 4; j++) acc[i][j] = 0ULL;

    const unsigned long long* xr0 = (const unsigned long long*)&xs[(rb + 0) * SX];
    const unsigned long long* xr1 = (const unsigned long long*)&xs[(rb + 1) * SX];
    const unsigned long long* xr2 = (const unsigned long long*)&xs[(rb + 2) * SX];
    const unsigned long long* xr3 = (const unsigned long long*)&xs[(rb + 3) * SX];

#pragma unroll 4
    for (int kp = 0; kp < 128; kp++) {
        unsigned long long w0 = ws[kp * SW + g0 + 0];
        unsigned long long w1 = ws[kp * SW + g0 + 8];
        unsigned long long w2 = ws[kp * SW + g0 + 16];
        unsigned long long w3 = ws[kp * SW + g0 + 24];
        unsigned long long xa = xr0[kp], xb = xr1[kp], xc = xr2[kp], xd = xr3[kp];
        fma2(acc[0][0], xa, w0); fma2(acc[0][1], xa, w1);
        fma2(acc[0][2], xa, w2); fma2(acc[0][3], xa, w3);
        fma2(acc[1][0], xb, w0); fma2(acc[1][1], xb, w1);
        fma2(acc[1][2], xb, w2); fma2(acc[1][3], xb, w3);
        fma2(acc[2][0], xc, w0); fma2(acc[2][1], xc, w1);
        fma2(acc[2][2], xc, w2); fma2(acc[2][3], xc, w3);
        fma2(acc[3][0], xd, w0); fma2(acc[3][1], xd, w1);
        fma2(acc[3][2], xd, w2); fma2(acc[3][3], xd, w3);
    }

    float bias[4];
#pragma unroll
    for (int j = 0; j < 4; j++) bias[j] = b_ih[g0 + 8 * j] + b_hh[g0 + 8 * j];
#pragma unroll
    for (int i = 0; i < 4; i++) {
#pragma unroll
        for (int j = 0; j < 4; j++) {
            unsigned lo = (unsigned)acc[i][j];
            unsigned hi = (unsigned)(acc[i][j] >> 32);
            float s = __uint_as_float(lo) + __uint_as_float(hi) + bias[j];
            g_xg[(row0 + rb + i) * G_DIM + g0 + 8 * j] = s;
        }
    }
}

// ---------------------------------------------------------------------------
// Sequential LSTM scan. One warp per batch element (256 warps total).
// lane = gate index (i: 0-7, f: 8-15, g: 16-23, o: 24-31).
// h[0..7] replicated across all lanes; per step:
//   gate = xg + keep * (W_hh[lane,:] . h)        (biases already folded)
//   act  = sigmoid/tanh via MUFU ex2 + rcp (accurate to ~1e-6)
//   shfl-gather i,f,g,o  ->  c' = f*(c*keep) + i*g ;  h = o * tanh(c')
//   shfl-broadcast h; projection off the critical path.
// ---------------------------------------------------------------------------
__global__ void __launch_bounds__(128) scan_k(
    const int* __restrict__ reset, const float* __restrict__ W_hh,
    const float* __restrict__ W_proj, const float* __restrict__ b_proj,
    float* __restrict__ out)
{
    const int lane = threadIdx.x & 31;
    const int b = (blockIdx.x * blockDim.x + threadIdx.x) >> 5;

    float w[8], wp[8];
#pragma unroll
    for (int j = 0; j < 8; j++) w[j] = W_hh[lane * 8 + j];
#pragma unroll
    for (int j = 0; j < 8; j++) wp[j] = W_proj[j];
    const float bp = b_proj[0];

    // sigmoid lanes: i, f, o ; tanh lanes: g (16..23)
    const bool sg = (lane < 16) || (lane >= 24);
    const float EB = sg ? -1.4426950408889634f : -2.8853900817779268f;
    const float AA = sg ? 1.0f : 2.0f;
    const float CC = sg ? 0.0f : -1.0f;

    const float* xp = g_xg + (size_t)b * G_DIM + lane;
    const int* rp = reset + b;

    float h[8];
#pragma unroll
    for (int j = 0; j < 8; j++) h[j] = 0.f;
    float cc = 0.f;

    // Prefetch ring, depth 4 (~4 steps * ~180cyc covers DRAM/L2 latency)
    float xv[4], kv[4];
#pragma unroll
    for (int i = 0; i < 4; i++) {
        xv[i] = xp[(size_t)i * (B_DIM * G_DIM)];
        kv[i] = 1.0f - (float)rp[(size_t)i * B_DIM];
    }

    for (int t = 0; t < T_DIM; t += 4) {
#pragma unroll
        for (int p = 0; p < 4; p++) {
            const int tt = t + p;
            const float xc = xv[p], keep = kv[p];
            if (tt + 4 < T_DIM) {
                xv[p] = xp[(size_t)(tt + 4) * (B_DIM * G_DIM)];
                kv[p] = 1.0f - (float)rp[(size_t)(tt + 4) * B_DIM];
            }
            // gate pre-activation
            float d0 = fmaf(w[1], h[1], w[0] * h[0]);
            d0 = fmaf(w[2], h[2], d0);
            d0 = fmaf(w[3], h[3], d0);
            float d1 = fmaf(w[5], h[5], w[4] * h[4]);
            d1 = fmaf(w[6], h[6], d1);
            d1 = fmaf(w[7], h[7], d1);
            float gate = fmaf(keep, d0 + d1, xc);
            float ck = cc * keep;
            // act = AA * 1/(1 + 2^(EB*gate)) + CC   (sigmoid or tanh)
            float act = fmaf(AA, rcpa(1.0f + ex2a(EB * gate)), CC);
            // gather the four gate groups into every lane (fully replicated)
            float iv = __shfl_sync(0xffffffffu, act, (lane & 7));
            float fv = __shfl_sync(0xffffffffu, act, (lane & 7) + 8);
            float gv = __shfl_sync(0xffffffffu, act, (lane & 7) + 16);
            float ov = __shfl_sync(0xffffffffu, act, (lane & 7) + 24);
            float cn = fmaf(fv, ck, iv * gv);
            float tc = fmaf(2.0f, rcpa(1.0f + ex2a(-2.8853900817779268f * cn)), -1.0f);
            float hv = ov * tc;   // lane L holds h_{L&7}
            cc = cn;
            // broadcast h[0..7] to all lanes
#pragma unroll
            for (int j = 0; j < 8; j++) h[j] = __shfl_sync(0xffffffffu, hv, j);
            // projection (off the recurrence critical path)
            float pv = bp;
#pragma unroll
            for (int j = 0; j < 8; j++) pv = fmaf(h[j], wp[j], pv);
            if (lane == 0) out[(size_t)tt * B_DIM + b] = pv;
        }
    }
}

// ---------------------------------------------------------------------------
extern "C" void kernel_launch(void* const* d_in, const int* in_sizes, int n_in,
                              void* d_out, int out_size)
{
    const float* x      = (const float*)d_in[0];
    const int*   reset  = (const int*)d_in[1];
    const float* W_ih   = (const float*)d_in[2];
    const float* W_hh   = (const float*)d_in[3];
    const float* b_ih   = (const float*)d_in[4];
    const float* b_hh   = (const float*)d_in[5];
    const float* W_proj = (const float*)d_in[6];
    const float* b_proj = (const float*)d_in[7];
    float* out = (float*)d_out;

    (void)in_sizes; (void)n_in; (void)out_size;

    cudaFuncSetAttribute(gemm_k, cudaFuncAttributeMaxDynamicSharedMemorySize,
                         GEMM_SMEM);
    gemm_k<<<M_DIM / GROWS, 128, GEMM_SMEM>>>(x, W_ih, b_ih, b_hh);
    // 256 warps = one per batch element; 64 blocks x 4 warps spreads over SMs
    scan_k<<<(B_DIM * 32) / 128, 128>>>(reset, W_hh, W_proj, b_proj, out);
}

// round 4
// speedup vs baseline: 1.9289x; 1.9289x over previous
#include <cuda_runtime.h>
#include <cstdint>

#define T_DIM 2048
#define B_DIM 256
#define D_DIM 256
#define H_DIM 8
#define G_DIM 32
#define M_DIM (T_DIM * B_DIM)

// Scratch for x_gates (+ folded biases): [T, B, 32] fp32 = 64 MB
__device__ float g_xg[(size_t)M_DIM * G_DIM];

// ---------------------------------------------------------------------------
// Packed f32x2 FMA (sm_103a): d = a*b + d  (two independent fp32 FMAs)
// ---------------------------------------------------------------------------
__device__ __forceinline__ void fma2(unsigned long long& d,
                                     unsigned long long a,
                                     unsigned long long b) {
    asm("fma.rn.f32x2 %0, %1, %2, %0;" : "+l"(d) : "l"(a), "l"(b));
}

__device__ __forceinline__ float ex2a(float x) {
    float y; asm("ex2.approx.ftz.f32 %0, %1;" : "=f"(y) : "f"(x)); return y;
}
__device__ __forceinline__ float rcpa(float x) {
    float y; asm("rcp.approx.ftz.f32 %0, %1;" : "=f"(y) : "f"(x)); return y;
}

// ---------------------------------------------------------------------------
// GEMM: x_gates[m, g] = sum_k x[m,k] * W_ih[g,k]  + (b_ih[g] + b_hh[g])
// (unchanged from R3 — known correct, ~330us; next optimization target)
// ---------------------------------------------------------------------------
#define GROWS 64
#define SX 258
#define SW 33
#define GEMM_SMEM (GROWS * SX * 4 + 128 * SW * 8)

__global__ void __launch_bounds__(128, 2) gemm_k(
    const float* __restrict__ x, const float* __restrict__ W_ih,
    const float* __restrict__ b_ih, const float* __restrict__ b_hh)
{
    extern __shared__ float sm[];
    float* xs = sm;                                                  // [64][SX]
    unsigned long long* ws = (unsigned long long*)(sm + GROWS * SX); // [128][SW]
    const int tid = threadIdx.x;
    const size_t row0 = (size_t)blockIdx.x * GROWS;

    const float2* W2 = (const float2*)W_ih;
    for (int u = tid; u < 32 * 128; u += 128) {
        int g = u >> 7, kp = u & 127;
        float2 v = W2[(size_t)g * 128 + kp];
        ((float2*)ws)[kp * SW + g] = v;
    }
    const float4* X4 = (const float4*)(x + row0 * D_DIM);
    for (int u = tid; u < GROWS * 64; u += 128) {
        int r = u >> 6, k4 = u & 63;
        float4 v = X4[(size_t)r * 64 + k4];
        float2* dst = (float2*)&xs[r * SX + k4 * 4];
        dst[0] = make_float2(v.x, v.y);
        dst[1] = make_float2(v.z, v.w);
    }
    __syncthreads();

    const int g0 = tid & 7;
    const int rb = (tid >> 3) * 4;

    unsigned long long acc[4][4];
#pragma unroll
    for (int i = 0; i < 4; i++)
#pragma unroll
        for (int j = 0; j < 4; j++) acc[i][j] = 0ULL;

    const unsigned long long* xr0 = (const unsigned long long*)&xs[(rb + 0) * SX];
    const unsigned long long* xr1 = (const unsigned long long*)&xs[(rb + 1) * SX];
    const unsigned long long* xr2 = (const unsigned long long*)&xs[(rb + 2) * SX];
    const unsigned long long* xr3 = (const unsigned long long*)&xs[(rb + 3) * SX];

#pragma unroll 4
    for (int kp = 0; kp < 128; kp++) {
        unsigned long long w0 = ws[kp * SW + g0 + 0];
        unsigned long long w1 = ws[kp * SW + g0 + 8];
        unsigned long long w2 = ws[kp * SW + g0 + 16];
        unsigned long long w3 = ws[kp * SW + g0 + 24];
        unsigned long long xa = xr0[kp], xb = xr1[kp], xc = xr2[kp], xd = xr3[kp];
        fma2(acc[0][0], xa, w0); fma2(acc[0][1], xa, w1);
        fma2(acc[0][2], xa, w2); fma2(acc[0][3], xa, w3);
        fma2(acc[1][0], xb, w0); fma2(acc[1][1], xb, w1);
        fma2(acc[1][2], xb, w2); fma2(acc[1][3], xb, w3);
        fma2(acc[2][0], xc, w0); fma2(acc[2][1], xc, w1);
        fma2(acc[2][2], xc, w2); fma2(acc[2][3], xc, w3);
        fma2(acc[3][0], xd, w0); fma2(acc[3][1], xd, w1);
        fma2(acc[3][2], xd, w2); fma2(acc[3][3], xd, w3);
    }

    float bias[4];
#pragma unroll
    for (int j = 0; j < 4; j++) bias[j] = b_ih[g0 + 8 * j] + b_hh[g0 + 8 * j];
#pragma unroll
    for (int i = 0; i < 4; i++) {
#pragma unroll
        for (int j = 0; j < 4; j++) {
            unsigned lo = (unsigned)acc[i][j];
            unsigned hi = (unsigned)(acc[i][j] >> 32);
            float s = __uint_as_float(lo) + __uint_as_float(hi) + bias[j];
            g_xg[(row0 + rb + i) * G_DIM + g0 + 8 * j] = s;
        }
    }
}

// ---------------------------------------------------------------------------
// Segment-parallel LSTM scan.
// reset==1 at (t,b) zeroes h,c BEFORE step t, so every reset begins an
// independent segment with h0=c0=0. One warp per (t,b): the warp exits
// unless (t==0 || reset[t,b]==1); otherwise it runs its whole segment
// (until the next reset / end of T). lane = gate index as before.
// keep==1 inside a segment, so the keep math vanishes.
// Segment end found via a 32-wide lane window of future resets + ballot,
// refilled every 32 steps (correct for arbitrarily long segments).
// ---------------------------------------------------------------------------
__global__ void __launch_bounds__(256) scan_seg_k(
    const int* __restrict__ reset,
    const float* __restrict__ W_hh, const float* __restrict__ W_proj,
    const float* __restrict__ b_proj, float* __restrict__ out)
{
    const int lane = threadIdx.x & 31;
    const int wid = (blockIdx.x * blockDim.x + threadIdx.x) >> 5;
    const int t0 = wid >> 8;    // time index  (T_DIM = 2048)
    const int b  = wid & 255;   // batch index (B_DIM = 256)

    // Segment-start check (warp-uniform): broadcast load of one int.
    const int rstart = reset[(size_t)t0 * B_DIM + b];
    if (t0 != 0 && rstart == 0) return;

    float w[8], wp[8];
#pragma unroll
    for (int j = 0; j < 8; j++) w[j] = W_hh[lane * 8 + j];
#pragma unroll
    for (int j = 0; j < 8; j++) wp[j] = W_proj[j];
    const float bp = b_proj[0];

    // sigmoid lanes: i (0-7), f (8-15), o (24-31); tanh lanes: g (16-23)
    const bool sg = (lane < 16) || (lane >= 24);
    const float EB = sg ? -1.4426950408889634f : -2.8853900817779268f;
    const float AA = sg ? 1.0f : 2.0f;
    const float CC = sg ? 0.0f : -1.0f;

    float h[8];
#pragma unroll
    for (int j = 0; j < 8; j++) h[j] = 0.f;
    float cc = 0.f;

    const float* xp = g_xg + (size_t)b * G_DIM + lane;
    float xcur = xp[(size_t)t0 * (B_DIM * G_DIM)];

    int base = t0;
    while (true) {
        // Window of resets for steps base .. base+31 (bit0 = base itself,
        // masked off: segment-start reset must not terminate its own segment,
        // and mid-segment window heads are known-zero).
        const int idx = base + lane;
        const int rw = (idx < T_DIM) ? reset[(size_t)idx * B_DIM + b] : 1;
        unsigned m = __ballot_sync(0xffffffffu, rw != 0) & 0xfffffffeu;
        const int cnt = m ? (__ffs((int)m) - 1) : 32;  // steps in this window

        for (int i = 0; i < cnt; i++) {
            const int tt = base + i;
            // prefetch next step's x_gates (harmless past segment end)
            float xnext = 0.f;
            if (tt + 1 < T_DIM) xnext = xp[(size_t)(tt + 1) * (B_DIM * G_DIM)];

            // gate pre-activation: xg + W_hh[lane,:] . h   (keep == 1)
            float d0 = fmaf(w[1], h[1], w[0] * h[0]);
            d0 = fmaf(w[2], h[2], d0);
            d0 = fmaf(w[3], h[3], d0);
            float d1 = fmaf(w[5], h[5], w[4] * h[4]);
            d1 = fmaf(w[6], h[6], d1);
            d1 = fmaf(w[7], h[7], d1);
            const float gate = xcur + (d0 + d1);
            // act = AA * 1/(1 + 2^(EB*gate)) + CC   (sigmoid or tanh)
            const float act = fmaf(AA, rcpa(1.0f + ex2a(EB * gate)), CC);
            // gather i,f,g,o for this lane's h-index
            const float iv = __shfl_sync(0xffffffffu, act, (lane & 7));
            const float fv = __shfl_sync(0xffffffffu, act, (lane & 7) + 8);
            const float gv = __shfl_sync(0xffffffffu, act, (lane & 7) + 16);
            const float ov = __shfl_sync(0xffffffffu, act, (lane & 7) + 24);
            const float cn = fmaf(fv, cc, iv * gv);
            const float tc = fmaf(2.0f,
                rcpa(1.0f + ex2a(-2.8853900817779268f * cn)), -1.0f);
            const float hv = ov * tc;   // lane L holds h_{L&7}
            cc = cn;
#pragma unroll
            for (int j = 0; j < 8; j++) h[j] = __shfl_sync(0xffffffffu, hv, j);
            // projection
            float pv = bp;
#pragma unroll
            for (int j = 0; j < 8; j++) pv = fmaf(h[j], wp[j], pv);
            if (lane == 0) out[(size_t)tt * B_DIM + b] = pv;
            xcur = xnext;
        }

        if (cnt < 32) return;   // next reset (or T end) terminates segment
        base += 32;             // rare: segment longer than window
    }
}

// ---------------------------------------------------------------------------
extern "C" void kernel_launch(void* const* d_in, const int* in_sizes, int n_in,
                              void* d_out, int out_size)
{
    const float* x      = (const float*)d_in[0];
    const int*   reset  = (const int*)d_in[1];
    const float* W_ih   = (const float*)d_in[2];
    const float* W_hh   = (const float*)d_in[3];
    const float* b_ih   = (const float*)d_in[4];
    const float* b_hh   = (const float*)d_in[5];
    const float* W_proj = (const float*)d_in[6];
    const float* b_proj = (const float*)d_in[7];
    float* out = (float*)d_out;

    (void)in_sizes; (void)n_in; (void)out_size;

    cudaFuncSetAttribute(gemm_k, cudaFuncAttributeMaxDynamicSharedMemorySize,
                         GEMM_SMEM);
    gemm_k<<<M_DIM / GROWS, 128, GEMM_SMEM>>>(x, W_ih, b_ih, b_hh);
    // one warp per (t, b): T*B warps, 8 warps (256 threads) per block
    scan_seg_k<<<(M_DIM * 32) / 256, 256>>>(reset, W_hh, W_proj, b_proj, out);
}